// round 16
// baseline (speedup 1.0000x reference)
#include <cuda_runtime.h>
#include <cuda_bf16.h>
#include <math.h>
#include <stdint.h>

#define B_     16
#define C_     3
#define H_     256
#define W_     256
#define WF     129
#define NPTS   (H_ * WF)
#define NRAD   32
#define NAZ    8
#define PI_F   3.14159265358979323846f
#define TWOPI_F 6.28318530717958647692f

#define FMA2(d, a, b) \
    asm("fma.rn.f32x2 %0, %1, %2, %0;" : "+l"(d) : "l"(a), "l"(b))

// tf32 mma.sync (baseline PTX, sm_80+; lowers to HMMA on sm_103)
#define MMA_TF32(c, a, b0v, b1v) \
    asm volatile("mma.sync.aligned.m16n8k8.row.col.f32.tf32.tf32.f32 " \
        "{%0,%1,%2,%3}, {%4,%5,%6,%7}, {%8,%9}, {%0,%1,%2,%3};" \
        : "+f"((c)[0]), "+f"((c)[1]), "+f"((c)[2]), "+f"((c)[3]) \
        : "r"((a)[0]), "r"((a)[1]), "r"((a)[2]), "r"((a)[3]), "r"(b0v), "r"(b1v))

// ------------------------- scratch (device globals) ------------------------
__device__ float2 g_freq [B_ * C_ * H_ * WF];
__device__ float  g_mag  [B_ * C_ * H_ * WF];
__device__ float  g_phase[B_ * C_ * H_ * WF];
__device__ float  g_magsp[B_ * C_ * H_ * W_];
__device__ float  g_phsp [B_ * C_ * H_ * W_];
__device__ float  g_featm[(size_t)B_ * 64 * H_ * W_];
__device__ float  g_featp[(size_t)B_ * 32 * H_ * W_];
__device__ float  g_radial[B_ * C_ * NRAD];
__device__ float  g_az    [B_ * NAZ * 2 * C_];
__device__ float  g_poolm [B_ * 64];
__device__ float  g_poolp [B_ * 32];

__device__ __forceinline__ float n2n(float v) {
    if (isnan(v)) return 0.f;
    if (isinf(v)) return v > 0.f ? 1e4f : -1e4f;
    return v;
}
__device__ __forceinline__ float tf32r(float x) {
    asm("cvt.rna.tf32.f32 %0, %0;" : "+f"(x));
    return x;
}

// ------------------------------ FFT (len 256) ------------------------------
__device__ __forceinline__ void fft256(float* re, float* im, const float2* stw, int t) {
    #pragma unroll
    for (int len = 2; len <= 256; len <<= 1) {
        int half = len >> 1, grp = t / half, pos = t - grp * half;
        int i0 = grp * len + pos, i1 = i0 + half;
        float2 w = stw[pos * (256 / len)];
        float ar = re[i0], ai = im[i0], br = re[i1], bi = im[i1];
        float tr = w.x * br - w.y * bi, ti = w.x * bi + w.y * br;
        re[i0] = ar + tr;  im[i0] = ai + ti;
        re[i1] = ar - tr;  im[i1] = ai - ti;
        __syncthreads();
    }
}
__device__ __forceinline__ void make_tw(float2* stw, int t) {
    double ang = -6.283185307179586476925286766559 * (double)t / 256.0;
    double s, c; sincos(ang, &s, &c);
    stw[t] = make_float2((float)c, (float)s);
}

__global__ void rowfft_kernel(const float* __restrict__ x) {
    int row = blockIdx.x;
    const float* px = x + (size_t)row * W_;
    __shared__ float sre[256], sim[256];
    __shared__ float2 stw[128];
    int t = threadIdx.x;
    make_tw(stw, t);
    if (row == 0) {
        for (int i = t; i < B_ * 64; i += 128) g_poolm[i] = 0.f;
        for (int i = t; i < B_ * 32; i += 128) g_poolp[i] = 0.f;
    }
    #pragma unroll
    for (int i = t; i < 256; i += 128) {
        float v = fminf(fmaxf(px[i], -10.f), 10.f);
        int r = (int)(__brev((unsigned)i) >> 24);
        sre[r] = v;  sim[r] = 0.f;
    }
    __syncthreads();
    fft256(sre, sim, stw, t);
    for (int i = t; i < WF; i += 128)
        g_freq[(size_t)row * WF + i] = make_float2(sre[i], sim[i]);
}

__global__ void colfft_kernel() {
    int col = blockIdx.x;
    int bc = col / WF, w = col - bc * WF;
    const float2* base = g_freq + (size_t)bc * H_ * WF + w;
    __shared__ float sre[256], sim[256];
    __shared__ float2 stw[128];
    int t = threadIdx.x;
    make_tw(stw, t);
    #pragma unroll
    for (int h = t; h < 256; h += 128) {
        float2 v = base[(size_t)h * WF];
        int r = (int)(__brev((unsigned)h) >> 24);
        sre[r] = v.x;  sim[r] = v.y;
    }
    __syncthreads();
    fft256(sre, sim, stw, t);
    const float INVPI = __fdiv_rn(1.f, PI_F);
    #pragma unroll
    for (int h = t; h < 256; h += 128) {
        float re_ = sre[h], im_ = sim[h];
        float m = hypotf(re_, im_);
        m = fminf(fmaxf(m, 1e-8f), 1e6f);
        float ph = __fmul_rn(atan2f(im_, re_), INVPI);
        ph = fminf(fmaxf(ph, -1.f), 1.f);
        size_t idx = (size_t)bc * NPTS + (size_t)h * WF + w;
        g_mag[idx] = m;  g_phase[idx] = ph;
    }
}

// -------------------- radial / azimuthal statistics ------------------------
__global__ void stats_kernel() {
    int bc = blockIdx.x, t = threadIdx.x;
    __shared__ float rs[NRAD], rc[NRAD], s1[NAZ], s2[NAZ], ac[NAZ];
    if (t < NRAD) { rs[t] = 0.f; rc[t] = 0.f; }
    if (t < NAZ)  { s1[t] = 0.f; s2[t] = 0.f; ac[t] = 0.f; }
    __syncthreads();
    const float rmax = __fsqrt_rn(0.5f);
    const float inv_denom = __fdiv_rn(1.f, __fadd_rn(rmax, 1e-8f));
    const float C8 = __fmul_rn(__fdiv_rn(1.f, TWOPI_F), 8.f);
    const float* magp = g_mag + (size_t)bc * NPTS;
    for (int n = t; n < NPTS; n += 256) {
        int i = n / WF, j = n - i * WF;
        float fy = (float)(i < 128 ? i : i - 256) * (1.f / 256.f);
        float fx = (float)j * (1.f / 256.f);
        float radius = __fsqrt_rn(__fadd_rn(__fmul_rn(fx, fx), __fmul_rn(fy, fy)));
        float rv = __fmul_rn(__fmul_rn(radius, inv_denom), 31.0f);
        int rb = min(max((int)rv, 0), NRAD - 1);
        float ang = atan2f(fy, __fadd_rn(fx, 1e-8f));
        float av = __fmul_rn(__fadd_rn(ang, PI_F), C8);
        int ab = min(max((int)av, 0), NAZ - 1);
        float m = magp[n];
        atomicAdd(&rs[rb], m);  atomicAdd(&rc[rb], 1.f);
        atomicAdd(&s1[ab], m);  atomicAdd(&s2[ab], __fmul_rn(m, m));
        atomicAdd(&ac[ab], 1.f);
    }
    __syncthreads();
    int b = bc / C_, c = bc - b * C_;
    if (t < NRAD) {
        float cnt = fmaxf(rc[t], 1.f);
        float v = __fmul_rn(rs[t], __fdiv_rn(1.f, cnt));
        g_radial[(b * C_ + c) * NRAD + t] = fminf(fmaxf(v, 0.f), 1e6f);
    }
    if (t < NAZ) {
        float cnt = ac[t], mean = 0.f, sd = 0.f;
        if (cnt > 0.f) {
            mean = __fmul_rn(s1[t], __fdiv_rn(1.f, cnt));
            float num = __fsub_rn(s2[t], __fmul_rn(cnt, __fmul_rn(mean, mean)));
            sd = __fsqrt_rn(fmaxf(__fmul_rn(num, __fdiv_rn(1.f, fmaxf(cnt - 1.f, 1.f))), 0.f));
        }
        g_az[b * (NAZ * 2 * C_) + t * (2 * C_) + c]      = n2n(mean);
        g_az[b * (NAZ * 2 * C_) + t * (2 * C_) + C_ + c] = n2n(sd);
    }
}

// ------------------------- bilinear resize 129 -> 256 ----------------------
__global__ void resize_kernel() {
    int idx = blockIdx.x * blockDim.x + threadIdx.x;
    if (idx >= B_ * C_ * H_ * W_) return;
    int xo = idx & 255, y = (idx >> 8) & 255, bc = idx >> 16;
    float sx = ((float)xo + 0.5f) * (129.f / 256.f) - 0.5f;
    float fl = floorf(sx);
    int j0 = (int)fl;
    float f = sx - fl;
    int ja = max(j0, 0), jb = min(j0 + 1, WF - 1);
    size_t rowbase = (size_t)bc * NPTS + (size_t)y * WF;
    float m0 = g_mag[rowbase + ja], m1 = g_mag[rowbase + jb];
    float l0 = fminf(fmaxf(log1pf(m0), -20.f), 20.f);
    float l1 = fminf(fmaxf(log1pf(m1), -20.f), 20.f);
    g_magsp[idx] = (1.f - f) * l0 + f * l1;
    float p0 = g_phase[rowbase + ja], p1 = g_phase[rowbase + jb];
    g_phsp[idx] = (1.f - f) * p0 + f * p1;
}

// -------------------- conv1: 3->Cout 3x3 + bn + relu (FMA2) ----------------
template <int CIN, int COPB>
__global__ void __launch_bounds__(256, 2)
conv3x3_kernel(const float* __restrict__ in, const float* __restrict__ wt,
               const float* __restrict__ bias, const float* __restrict__ bn,
               float* __restrict__ outFeat, int Cout)
{
    constexpr int NP = COPB / 2;
    const int groups = Cout / COPB;
    const int b = blockIdx.z / groups, g = blockIdx.z - b * groups;
    const int coB = g * COPB;
    const int x0 = blockIdx.x * 32, y0 = blockIdx.y * 32;
    const int tid = threadIdx.x;
    const int tx = (tid & 15) * 2, ty = (tid >> 4) * 2;
    __shared__ float  s_in[34 * 34];
    __shared__ float2 s_w2[CIN * 9 * NP];
    for (int idx = tid; idx < COPB * CIN * 9; idx += 256) {
        int c = idx / (CIN * 9), r = idx - c * (CIN * 9);
        reinterpret_cast<float*>(&s_w2[r * NP + (c >> 1)])[c & 1] =
            wt[(size_t)(coB + c) * CIN * 9 + r];
    }
    unsigned long long acc2[NP][4];
    #pragma unroll
    for (int cp = 0; cp < NP; ++cp)
        acc2[cp][0] = acc2[cp][1] = acc2[cp][2] = acc2[cp][3] = 0ull;
    for (int ci = 0; ci < CIN; ++ci) {
        const float* plane = in + ((size_t)(b * CIN + ci)) * (H_ * W_);
        __syncthreads();
        for (int idx = tid; idx < 34 * 34; idx += 256) {
            int iy = idx / 34, ix = idx - iy * 34;
            int gy = y0 + iy - 1, gx = x0 + ix - 1;
            s_in[idx] = (gy >= 0 && gy < H_ && gx >= 0 && gx < W_)
                        ? plane[gy * W_ + gx] : 0.f;
        }
        __syncthreads();
        unsigned long long vv[16];
        #pragma unroll
        for (int dy = 0; dy < 4; ++dy)
            #pragma unroll
            for (int dx = 0; dx < 4; ++dx) {
                float v = s_in[(ty + dy) * 34 + tx + dx];
                asm("mov.b64 %0, {%1, %1};" : "=l"(vv[dy * 4 + dx]) : "f"(v));
            }
        const float2* wbase = &s_w2[ci * 9 * NP];
        #pragma unroll
        for (int cp = 0; cp < NP; ++cp) {
            #pragma unroll
            for (int k = 0; k < 9; ++k) {
                int dy = k / 3, dx = k - dy * 3;
                unsigned long long wp =
                    *reinterpret_cast<const unsigned long long*>(&wbase[k * NP + cp]);
                FMA2(acc2[cp][0], wp, vv[dy * 4 + dx]);
                FMA2(acc2[cp][1], wp, vv[dy * 4 + dx + 1]);
                FMA2(acc2[cp][2], wp, vv[(dy + 1) * 4 + dx]);
                FMA2(acc2[cp][3], wp, vv[(dy + 1) * 4 + dx + 1]);
            }
        }
    }
    #pragma unroll
    for (int cp = 0; cp < NP; ++cp)
        #pragma unroll
        for (int l = 0; l < 2; ++l) {
            int co = coB + 2 * cp + l;
            float gg = bn[co], bb = bn[Cout + co];
            float mm = bn[2 * Cout + co], vv_ = bn[3 * Cout + co];
            float sc = gg / sqrtf(vv_ + 1e-5f);
            float bi = bias[co];
            #pragma unroll
            for (int p = 0; p < 4; ++p) {
                float lo, hi;
                asm("mov.b64 {%0, %1}, %2;" : "=f"(lo), "=f"(hi) : "l"(acc2[cp][p]));
                float a = l ? hi : lo;
                float yv = fmaxf((a + bi - mm) * sc + bb, 0.f);
                int py = ty + (p >> 1), px = tx + (p & 1);
                outFeat[(((size_t)(b * Cout + co)) * H_ + (y0 + py)) * W_ + (x0 + px)] = yv;
            }
        }
}

// ------ conv2: implicit GEMM on mma.sync tf32, fused bn+relu+pool ----------
// Tile (b, y, xhalf): M=128 px, N=CO, K=CI per tap. Weights for all 9 taps
// staged once per persistent CTA as [tap][co][ci] (ci pitch CI+4, bank-clean).
// Per dy: stage one 130xCI input row; 3 dx taps read it with +-1 px shift.
template <int CO, int CI>
__global__ void __launch_bounds__(128, 1)
conv2_mma(const float* __restrict__ in, const float* __restrict__ wt,
          const float* __restrict__ bias, const float* __restrict__ bn,
          float* __restrict__ gpool, int nTiles, int tilesPer)
{
    constexpr int CIP = CI + 4;
    constexpr int NT  = CO / 8;
    constexpr int KS  = CI / 8;
    extern __shared__ float sm[];
    float* sA = sm;                       // [130][CIP]
    float* sB = sm + 130 * CIP;           // [9][CO][CIP]
    __shared__ float s_pool[CO], s_sc[CO], s_b1[CO], s_b2[CO];

    const int tid = threadIdx.x, w = tid >> 5, ln = tid & 31;
    const int lr = ln >> 2, lc = ln & 3;

    for (int i = tid; i < 9 * CO * CI; i += 128) {
        int tap = i / (CO * CI), r = i - tap * CO * CI;
        int co = r / CI, ci = r - co * CI;
        sB[(tap * CO + co) * CIP + ci] = tf32r(wt[(size_t)(co * CI + ci) * 9 + tap]);
    }
    if (tid < CO) {
        float gg = bn[tid], bb = bn[CO + tid], mm = bn[2 * CO + tid], vv = bn[3 * CO + tid];
        s_sc[tid] = gg / sqrtf(vv + 1e-5f);
        s_b1[tid] = bias[tid] - mm;
        s_b2[tid] = bb;
    }
    __syncthreads();

    for (int it = 0; it < tilesPer; ++it) {
        int tile = blockIdx.x * tilesPer + it;
        if (tile >= nTiles) break;
        int xh = tile & 1, y = (tile >> 1) & 255, b = tile >> 9;
        int x0 = xh * 128;

        float acc[2][NT][4];
        #pragma unroll
        for (int mt = 0; mt < 2; ++mt)
            #pragma unroll
            for (int nt = 0; nt < NT; ++nt)
                acc[mt][nt][0] = acc[mt][nt][1] = acc[mt][nt][2] = acc[mt][nt][3] = 0.f;
        if (tid < CO) s_pool[tid] = 0.f;

        for (int dy = 0; dy < 3; ++dy) {
            int row = y + dy - 1;
            bool rok = (row >= 0) && (row < H_);
            __syncthreads();                       // sA reuse + s_pool zero vis
            if (rok) {
                for (int i = tid; i < 130 * CI; i += 128) {
                    int ci = i / 130, px = i - ci * 130;
                    int x = x0 + px - 1;
                    float v = 0.f;
                    if (x >= 0 && x < W_)
                        v = tf32r(in[((size_t)(b * CI + ci) * H_ + row) * W_ + x]);
                    sA[px * CIP + ci] = v;
                }
            }
            __syncthreads();
            if (!rok) continue;

            #pragma unroll
            for (int dx = 0; dx < 3; ++dx) {
                const float* Bt = sB + (dy * 3 + dx) * CO * CIP;
                #pragma unroll
                for (int ks = 0; ks < KS; ++ks) {
                    int ci0 = ks * 8;
                    uint32_t a[2][4];
                    #pragma unroll
                    for (int mt = 0; mt < 2; ++mt) {
                        const float* ap = sA + (w * 32 + mt * 16 + lr + dx) * CIP + ci0 + lc;
                        a[mt][0] = __float_as_uint(ap[0]);
                        a[mt][1] = __float_as_uint(ap[8 * CIP]);
                        a[mt][2] = __float_as_uint(ap[4]);
                        a[mt][3] = __float_as_uint(ap[8 * CIP + 4]);
                    }
                    #pragma unroll
                    for (int nt = 0; nt < NT; ++nt) {
                        const float* bp = Bt + (nt * 8 + lr) * CIP + ci0 + lc;
                        uint32_t b0 = __float_as_uint(bp[0]);
                        uint32_t b1 = __float_as_uint(bp[4]);
                        MMA_TF32(acc[0][nt], a[0], b0, b1);
                        MMA_TF32(acc[1][nt], a[1], b0, b1);
                    }
                }
            }
        }

        // epilogue: bn+relu per element, reduce over px, pool
        #pragma unroll
        for (int nt = 0; nt < NT; ++nt) {
            int co0 = nt * 8 + 2 * lc, co1 = co0 + 1;
            float sc0 = s_sc[co0], b10 = s_b1[co0], b20 = s_b2[co0];
            float sc1 = s_sc[co1], b11 = s_b1[co1], b21 = s_b2[co1];
            float ve = fmaxf((acc[0][nt][0] + b10) * sc0 + b20, 0.f)
                     + fmaxf((acc[0][nt][2] + b10) * sc0 + b20, 0.f)
                     + fmaxf((acc[1][nt][0] + b10) * sc0 + b20, 0.f)
                     + fmaxf((acc[1][nt][2] + b10) * sc0 + b20, 0.f);
            float vo = fmaxf((acc[0][nt][1] + b11) * sc1 + b21, 0.f)
                     + fmaxf((acc[0][nt][3] + b11) * sc1 + b21, 0.f)
                     + fmaxf((acc[1][nt][1] + b11) * sc1 + b21, 0.f)
                     + fmaxf((acc[1][nt][3] + b11) * sc1 + b21, 0.f);
            #pragma unroll
            for (int o = 4; o < 32; o <<= 1) {
                ve += __shfl_xor_sync(0xffffffffu, ve, o);
                vo += __shfl_xor_sync(0xffffffffu, vo, o);
            }
            if (lr == 0) {
                atomicAdd(&s_pool[co0], ve);
                atomicAdd(&s_pool[co1], vo);
            }
        }
        __syncthreads();
        if (tid < CO) atomicAdd(&gpool[b * CO + tid], s_pool[tid]);
        __syncthreads();
    }
}

// -------------- conv1d branch + concat + MLP head + LayerNorm --------------
__global__ void final_kernel(const float* __restrict__ rw1, const float* __restrict__ rb1,
                             const float* __restrict__ rbn1, const float* __restrict__ rw2,
                             const float* __restrict__ rb2, const float* __restrict__ rbn2,
                             const float* __restrict__ lw1, const float* __restrict__ lb1,
                             const float* __restrict__ lng, const float* __restrict__ lnb,
                             const float* __restrict__ lw2, const float* __restrict__ lb2,
                             float* __restrict__ out)
{
    int b = blockIdx.x, t = threadIdx.x;
    __shared__ float s_r0[96], s_r1[1024], s_r2[1024];
    __shared__ float s_comb[176], s_h[256], s_red[256];
    if (t < 96) s_r0[t] = g_radial[b * 96 + t];
    __syncthreads();
    for (int idx = t; idx < 1024; idx += 256) {
        int co = idx >> 5, i = idx & 31;
        float s = rb1[co];
        #pragma unroll
        for (int ci = 0; ci < 3; ++ci) {
            const float* wp = &rw1[(co * 3 + ci) * 3];
            if (i > 0)  s += wp[0] * s_r0[ci * 32 + i - 1];
            s += wp[1] * s_r0[ci * 32 + i];
            if (i < 31) s += wp[2] * s_r0[ci * 32 + i + 1];
        }
        float gg = rbn1[co], bb = rbn1[32 + co], mm = rbn1[64 + co], vv = rbn1[96 + co];
        s_r1[idx] = fmaxf((s - mm) * (gg / sqrtf(vv + 1e-5f)) + bb, 0.f);
    }
    __syncthreads();
    for (int idx = t; idx < 1024; idx += 256) {
        int co = idx >> 5, i = idx & 31;
        float s = rb2[co];
        for (int ci = 0; ci < 32; ++ci) {
            const float* wp = &rw2[(co * 32 + ci) * 3];
            const float* rp = &s_r1[ci * 32 + i];
            if (i > 0)  s += wp[0] * rp[-1];
            s += wp[1] * rp[0];
            if (i < 31) s += wp[2] * rp[1];
        }
        float gg = rbn2[co], bb = rbn2[32 + co], mm = rbn2[64 + co], vv = rbn2[96 + co];
        s_r2[idx] = fmaxf((s - mm) * (gg / sqrtf(vv + 1e-5f)) + bb, 0.f);
    }
    __syncthreads();
    if (t < 64) {
        s_comb[t] = n2n(g_poolm[b * 64 + t] * (1.f / 65536.f));
    } else if (t < 96) {
        s_comb[t] = n2n(g_poolp[b * 32 + (t - 64)] * (1.f / 65536.f));
    } else if (t < 128) {
        int co = t - 96;
        float s = 0.f;
        #pragma unroll
        for (int i = 0; i < 32; ++i) s += s_r2[co * 32 + i];
        s_comb[t] = n2n(s * (1.f / 32.f));
    } else if (t < 176) {
        s_comb[t] = n2n(g_az[b * 48 + (t - 128)]);
    }
    __syncthreads();
    float hv = lb1[t];
    for (int k = 0; k < 176; ++k) hv += lw1[t * 176 + k] * s_comb[k];
    s_red[t] = hv;
    __syncthreads();
    #pragma unroll
    for (int o = 128; o; o >>= 1) { if (t < o) s_red[t] += s_red[t + o]; __syncthreads(); }
    float mu = s_red[0] * (1.f / 256.f);
    __syncthreads();
    float d = hv - mu;
    s_red[t] = d * d;
    __syncthreads();
    #pragma unroll
    for (int o = 128; o; o >>= 1) { if (t < o) s_red[t] += s_red[t + o]; __syncthreads(); }
    float var = s_red[0] * (1.f / 256.f);
    __syncthreads();
    s_h[t] = fmaxf(d / sqrtf(var + 1e-5f) * lng[t] + lnb[t], 0.f);
    __syncthreads();
    if (t < 128) {
        float o = lb2[t];
        for (int j = 0; j < 256; ++j) o += lw2[t * 256 + j] * s_h[j];
        if (isnan(o)) o = 0.f;
        else o = fminf(fmaxf(o, -100.f), 100.f);
        out[b * 128 + t] = o;
    }
}

// --------------------------------- launch ----------------------------------
extern "C" void kernel_launch(void* const* d_in, const int* in_sizes, int n_in,
                              void* d_out, int out_size)
{
    const float* x    = (const float*)d_in[0];
    const float* mw1  = (const float*)d_in[1];
    const float* mb1  = (const float*)d_in[2];
    const float* mbn1 = (const float*)d_in[3];
    const float* mw2  = (const float*)d_in[4];
    const float* mb2  = (const float*)d_in[5];
    const float* mbn2 = (const float*)d_in[6];
    const float* pw1  = (const float*)d_in[7];
    const float* pb1  = (const float*)d_in[8];
    const float* pbn1 = (const float*)d_in[9];
    const float* pw2  = (const float*)d_in[10];
    const float* pb2  = (const float*)d_in[11];
    const float* pbn2 = (const float*)d_in[12];
    const float* rw1  = (const float*)d_in[13];
    const float* rb1  = (const float*)d_in[14];
    const float* rbn1 = (const float*)d_in[15];
    const float* rw2  = (const float*)d_in[16];
    const float* rb2  = (const float*)d_in[17];
    const float* rbn2 = (const float*)d_in[18];
    const float* lw1  = (const float*)d_in[19];
    const float* lb1  = (const float*)d_in[20];
    const float* lng  = (const float*)d_in[21];
    const float* lnb  = (const float*)d_in[22];
    const float* lw2  = (const float*)d_in[23];
    const float* lb2  = (const float*)d_in[24];

    float *p_magsp, *p_phsp, *p_featm, *p_featp, *p_poolm, *p_poolp;
    cudaGetSymbolAddress((void**)&p_magsp, g_magsp);
    cudaGetSymbolAddress((void**)&p_phsp,  g_phsp);
    cudaGetSymbolAddress((void**)&p_featm, g_featm);
    cudaGetSymbolAddress((void**)&p_featp, g_featp);
    cudaGetSymbolAddress((void**)&p_poolm, g_poolm);
    cudaGetSymbolAddress((void**)&p_poolp, g_poolp);

    const int smem_m = (130 * 68 + 9 * 64 * 68) * 4;   // 192,032 B
    const int smem_p = (130 * 36 + 9 * 32 * 36) * 4;   //  60,192 B
    cudaFuncSetAttribute(conv2_mma<64, 64>, cudaFuncAttributeMaxDynamicSharedMemorySize, smem_m);
    cudaFuncSetAttribute(conv2_mma<32, 32>, cudaFuncAttributeMaxDynamicSharedMemorySize, smem_p);

    const int nTiles = B_ * H_ * 2;                    // 8192

    rowfft_kernel<<<B_ * C_ * H_, 128>>>(x);
    colfft_kernel<<<B_ * C_ * WF, 128>>>();
    resize_kernel<<<(B_ * C_ * H_ * W_ + 255) / 256, 256>>>();
    conv3x3_kernel<3, 16><<<dim3(8, 8, B_ * 4), 256>>>(p_magsp, mw1, mb1, mbn1, p_featm, 64);
    conv2_mma<64, 64><<<1024, 128, smem_m>>>(p_featm, mw2, mb2, mbn2, p_poolm, nTiles, 8);
    conv3x3_kernel<3, 16><<<dim3(8, 8, B_ * 2), 256>>>(p_phsp,  pw1, pb1, pbn1, p_featp, 32);
    conv2_mma<32, 32><<<1024, 128, smem_p>>>(p_featp, pw2, pb2, pbn2, p_poolp, nTiles, 8);
    stats_kernel<<<B_ * C_, 256>>>();
    final_kernel<<<B_, 256>>>(rw1, rb1, rbn1, rw2, rb2, rbn2,
                              lw1, lb1, lng, lnb, lw2, lb2, (float*)d_out);
}